// round 11
// baseline (speedup 1.0000x reference)
#include <cuda_runtime.h>
#include <cuda_bf16.h>

// SparseLinear: out[b,k] = dot(embed[b,:], weight[shortlist[b,k],:]) + bias[shortlist[b,k]]
// B=256, K=500, D=512, L=262144  (shortlist buffer is int32: JAX x64 disabled)
//
// R9 post-mortem: 55.8us, DRAM 50.5%, 4.0 TB/s — latency-limited, not BW-limited.
// Per-warp serial chain (idx load -> 4 LDG -> FMA -> 5 dependent SHFL) leaves
// loads out of flight ~half the time. R10: prefetch all indices per warp up
// front + software-pipeline the row loads (issue row i+1's LDG.128s before
// reducing row i) so weight loads stay in flight ~100% of the time.

#define B_DIM 256
#define K_DIM 500
#define D_DIM 512
#define SPLITS 8
#define K_PER_BLOCK ((K_DIM + SPLITS - 1) / SPLITS)   // 63
#define THREADS 256
#define WARPS (THREADS / 32)                          // 8
#define MAX_ITERS ((K_PER_BLOCK + WARPS - 1) / WARPS) // 8

__global__ __launch_bounds__(THREADS)
void sparse_linear_kernel(const float* __restrict__ embed,
                          const int* __restrict__ shortlist,
                          const float* __restrict__ weight,
                          const float* __restrict__ bias,
                          float* __restrict__ out)
{
    __shared__ float4 s_embed[D_DIM / 4];   // 128 float4 = 2KB

    const int b    = blockIdx.x;
    const int tid  = threadIdx.x;
    const int warp = tid >> 5;
    const int lane = tid & 31;

    // Cooperative load of embed[b] into smem (threads 0..127, one float4 each)
    const float4* embed_row = reinterpret_cast<const float4*>(embed + (size_t)b * D_DIM);
    if (tid < D_DIM / 4) {
        s_embed[tid] = embed_row[tid];
    }
    __syncthreads();

    const int k_begin = blockIdx.y * K_PER_BLOCK;
    int k_end = k_begin + K_PER_BLOCK;
    if (k_end > K_DIM) k_end = K_DIM;

    const int* sl_row = shortlist + (size_t)b * K_DIM;
    const int k0 = k_begin + warp;   // this warp's first k; stride = WARPS

    // ---- Phase 0: prefetch ALL indices for this warp (independent broadcast LDGs)
    int idxs[MAX_ITERS];
    #pragma unroll
    for (int i = 0; i < MAX_ITERS; i++) {
        const int k = k0 + i * WARPS;
        idxs[i] = (k < k_end) ? __ldg(sl_row + k) : 0;
    }

    if (k0 >= k_end) return;

    // Keep embed slice for this lane in registers (loop-invariant)
    const float4 e0 = s_embed[lane +  0];
    const float4 e1 = s_embed[lane + 32];
    const float4 e2 = s_embed[lane + 64];
    const float4 e3 = s_embed[lane + 96];

    // ---- Phase 1: preload row 0 (+ its bias)
    float4 w0, w1, w2, w3;
    float  bv;
    {
        const float4* wrow = reinterpret_cast<const float4*>(weight + (size_t)idxs[0] * D_DIM);
        w0 = wrow[lane +  0];
        w1 = wrow[lane + 32];
        w2 = wrow[lane + 64];
        w3 = wrow[lane + 96];
        bv = __ldg(bias + idxs[0]);
    }

    // ---- Phase 2: pipelined main loop — prefetch row i+1, compute row i
    #pragma unroll
    for (int i = 0; i < MAX_ITERS; i++) {
        const int k = k0 + i * WARPS;
        if (k >= k_end) break;

        const bool has_next = (k + WARPS < k_end) && (i + 1 < MAX_ITERS);

        // Prefetch next row + bias while current row's data is consumed below.
        float4 n0, n1, n2, n3;
        float  nbv = 0.0f;
        if (has_next) {
            const float4* nrow =
                reinterpret_cast<const float4*>(weight + (size_t)idxs[i + 1] * D_DIM);
            n0 = nrow[lane +  0];
            n1 = nrow[lane + 32];
            n2 = nrow[lane + 64];
            n3 = nrow[lane + 96];
            nbv = __ldg(bias + idxs[i + 1]);
        }

        // Compute current row's partial dot
        float sum = w0.x * e0.x + w0.y * e0.y + w0.z * e0.z + w0.w * e0.w;
        sum      += w1.x * e1.x + w1.y * e1.y + w1.z * e1.z + w1.w * e1.w;
        sum      += w2.x * e2.x + w2.y * e2.y + w2.z * e2.z + w2.w * e2.w;
        sum      += w3.x * e3.x + w3.y * e3.y + w3.z * e3.z + w3.w * e3.w;

        // Warp butterfly reduction (overlaps with the prefetch loads in flight)
        #pragma unroll
        for (int off = 16; off > 0; off >>= 1)
            sum += __shfl_xor_sync(0xFFFFFFFFu, sum, off);

        if (lane == 0)
            out[(size_t)b * K_DIM + k] = sum + bv;

        // Rotate pipeline registers
        w0 = n0; w1 = n1; w2 = n2; w3 = n3; bv = nbv;
    }
}

extern "C" void kernel_launch(void* const* d_in, const int* in_sizes, int n_in,
                              void* d_out, int out_size)
{
    const float* embed     = (const float*)d_in[0];  // [B, D] f32
    const int*   shortlist = (const int*)d_in[1];    // [B, K] i32
    const float* weight    = (const float*)d_in[2];  // [L, D] f32
    const float* bias      = (const float*)d_in[3];  // [L, 1] f32
    float*       out       = (float*)d_out;          // [B, K] f32

    dim3 grid(B_DIM, SPLITS);
    sparse_linear_kernel<<<grid, THREADS>>>(embed, shortlist, weight, bias, out);
}

// round 12
// speedup vs baseline: 1.0066x; 1.0066x over previous
#include <cuda_runtime.h>
#include <cuda_bf16.h>

// SparseLinear: out[b,k] = dot(embed[b,:], weight[shortlist[b,k],:]) + bias[shortlist[b,k]]
// B=256, K=500, D=512, L=262144  (shortlist buffer is int32: JAX x64 disabled)
//
// R9 post-mortem: 55.8us, DRAM 50.5%, 4.0 TB/s — latency-limited, not BW-limited.
// Per-warp serial chain (idx load -> 4 LDG -> FMA -> 5 dependent SHFL) leaves
// loads out of flight ~half the time. R10: prefetch all indices per warp up
// front + software-pipeline the row loads (issue row i+1's LDG.128s before
// reducing row i) so weight loads stay in flight ~100% of the time.

#define B_DIM 256
#define K_DIM 500
#define D_DIM 512
#define SPLITS 8
#define K_PER_BLOCK ((K_DIM + SPLITS - 1) / SPLITS)   // 63
#define THREADS 256
#define WARPS (THREADS / 32)                          // 8
#define MAX_ITERS ((K_PER_BLOCK + WARPS - 1) / WARPS) // 8

__global__ __launch_bounds__(THREADS)
void sparse_linear_kernel(const float* __restrict__ embed,
                          const int* __restrict__ shortlist,
                          const float* __restrict__ weight,
                          const float* __restrict__ bias,
                          float* __restrict__ out)
{
    __shared__ float4 s_embed[D_DIM / 4];   // 128 float4 = 2KB

    const int b    = blockIdx.x;
    const int tid  = threadIdx.x;
    const int warp = tid >> 5;
    const int lane = tid & 31;

    // Cooperative load of embed[b] into smem (threads 0..127, one float4 each)
    const float4* embed_row = reinterpret_cast<const float4*>(embed + (size_t)b * D_DIM);
    if (tid < D_DIM / 4) {
        s_embed[tid] = embed_row[tid];
    }
    __syncthreads();

    const int k_begin = blockIdx.y * K_PER_BLOCK;
    int k_end = k_begin + K_PER_BLOCK;
    if (k_end > K_DIM) k_end = K_DIM;

    const int* sl_row = shortlist + (size_t)b * K_DIM;
    const int k0 = k_begin + warp;   // this warp's first k; stride = WARPS

    // ---- Phase 0: prefetch ALL indices for this warp (independent broadcast LDGs)
    int idxs[MAX_ITERS];
    #pragma unroll
    for (int i = 0; i < MAX_ITERS; i++) {
        const int k = k0 + i * WARPS;
        idxs[i] = (k < k_end) ? __ldg(sl_row + k) : 0;
    }

    if (k0 >= k_end) return;

    // Keep embed slice for this lane in registers (loop-invariant)
    const float4 e0 = s_embed[lane +  0];
    const float4 e1 = s_embed[lane + 32];
    const float4 e2 = s_embed[lane + 64];
    const float4 e3 = s_embed[lane + 96];

    // ---- Phase 1: preload row 0 (+ its bias)
    float4 w0, w1, w2, w3;
    float  bv;
    {
        const float4* wrow = reinterpret_cast<const float4*>(weight + (size_t)idxs[0] * D_DIM);
        w0 = wrow[lane +  0];
        w1 = wrow[lane + 32];
        w2 = wrow[lane + 64];
        w3 = wrow[lane + 96];
        bv = __ldg(bias + idxs[0]);
    }

    // ---- Phase 2: pipelined main loop — prefetch row i+1, compute row i
    #pragma unroll
    for (int i = 0; i < MAX_ITERS; i++) {
        const int k = k0 + i * WARPS;
        if (k >= k_end) break;

        const bool has_next = (k + WARPS < k_end) && (i + 1 < MAX_ITERS);

        // Prefetch next row + bias while current row's data is consumed below.
        float4 n0, n1, n2, n3;
        float  nbv = 0.0f;
        if (has_next) {
            const float4* nrow =
                reinterpret_cast<const float4*>(weight + (size_t)idxs[i + 1] * D_DIM);
            n0 = nrow[lane +  0];
            n1 = nrow[lane + 32];
            n2 = nrow[lane + 64];
            n3 = nrow[lane + 96];
            nbv = __ldg(bias + idxs[i + 1]);
        }

        // Compute current row's partial dot
        float sum = w0.x * e0.x + w0.y * e0.y + w0.z * e0.z + w0.w * e0.w;
        sum      += w1.x * e1.x + w1.y * e1.y + w1.z * e1.z + w1.w * e1.w;
        sum      += w2.x * e2.x + w2.y * e2.y + w2.z * e2.z + w2.w * e2.w;
        sum      += w3.x * e3.x + w3.y * e3.y + w3.z * e3.z + w3.w * e3.w;

        // Warp butterfly reduction (overlaps with the prefetch loads in flight)
        #pragma unroll
        for (int off = 16; off > 0; off >>= 1)
            sum += __shfl_xor_sync(0xFFFFFFFFu, sum, off);

        if (lane == 0)
            out[(size_t)b * K_DIM + k] = sum + bv;

        // Rotate pipeline registers
        w0 = n0; w1 = n1; w2 = n2; w3 = n3; bv = nbv;
    }
}

extern "C" void kernel_launch(void* const* d_in, const int* in_sizes, int n_in,
                              void* d_out, int out_size)
{
    const float* embed     = (const float*)d_in[0];  // [B, D] f32
    const int*   shortlist = (const int*)d_in[1];    // [B, K] i32
    const float* weight    = (const float*)d_in[2];  // [L, D] f32
    const float* bias      = (const float*)d_in[3];  // [L, 1] f32
    float*       out       = (float*)d_out;          // [B, K] f32

    dim3 grid(B_DIM, SPLITS);
    sparse_linear_kernel<<<grid, THREADS>>>(embed, shortlist, weight, bias, out);
}

// round 13
// speedup vs baseline: 1.0491x; 1.0422x over previous
#include <cuda_runtime.h>
#include <cstdint>

// SparseLinear: out[b,k] = dot(embed[b,:], weight[shortlist[b,k],:]) + bias[shortlist[b,k]]
// B=256, K=500, D=512, L=262144  (shortlist buffer is int32: JAX x64 disabled)
//
// R10 post-mortem: 43.5us, DRAM 67.7% — still latency-exposed; register
// double-buffer caps in-flight depth at 1 row/warp and costs occupancy.
// R12: cp.async.cg -> smem 4-deep per-warp ring. Depth now paid in smem, not
// registers: 24 warps/SM x 4 rows x 2KB ~ 192KB in flight per SM. Each lane
// copies and consumes ONLY its own 16B slots -> wait_group alone synchronizes,
// no cross-lane barriers in the loop.

#define B_DIM 256
#define K_DIM 500
#define D_DIM 512
#define SPLITS 16
#define K_PER_BLOCK ((K_DIM + SPLITS - 1) / SPLITS)   // 32
#define THREADS 128
#define WARPS (THREADS / 32)                          // 4
#define MAX_ITERS ((K_PER_BLOCK + WARPS - 1) / WARPS) // 8
#define STAGES 4
#define ROW_F4 (D_DIM / 4)                            // 128 float4 per row

__device__ __forceinline__ void cp_async16(uint32_t saddr, const void* gaddr) {
    asm volatile("cp.async.cg.shared.global [%0], [%1], 16;\n"
                 :: "r"(saddr), "l"(gaddr) : "memory");
}
__device__ __forceinline__ void cp_commit() {
    asm volatile("cp.async.commit_group;\n" ::: "memory");
}
template <int N>
__device__ __forceinline__ void cp_wait() {
    asm volatile("cp.async.wait_group %0;\n" :: "n"(N) : "memory");
}

__global__ __launch_bounds__(THREADS)
void sparse_linear_kernel(const float* __restrict__ embed,
                          const int* __restrict__ shortlist,
                          const float* __restrict__ weight,
                          const float* __restrict__ bias,
                          float* __restrict__ out)
{
    __shared__ float4 s_embed[ROW_F4];                    // 2 KB
    __shared__ float4 s_rows[WARPS][STAGES][ROW_F4];      // 32 KB

    const int b    = blockIdx.x;
    const int tid  = threadIdx.x;
    const int warp = tid >> 5;
    const int lane = tid & 31;

    // Cooperative load of embed[b] into smem (128 threads, one float4 each)
    const float4* embed_row = reinterpret_cast<const float4*>(embed + (size_t)b * D_DIM);
    s_embed[tid] = embed_row[tid];
    __syncthreads();

    const int k_begin = blockIdx.y * K_PER_BLOCK;
    int k_end = k_begin + K_PER_BLOCK;
    if (k_end > K_DIM) k_end = K_DIM;

    const int* sl_row = shortlist + (size_t)b * K_DIM;
    const int k0 = k_begin + warp;             // this warp's first k; stride = WARPS

    // ---- Prefetch all indices + biases for this warp (independent LDGs)
    int   idxs[MAX_ITERS];
    float bvs[MAX_ITERS];
    int   n = 0;
    #pragma unroll
    for (int i = 0; i < MAX_ITERS; i++) {
        const int k = k0 + i * WARPS;
        if (k < k_end) { idxs[i] = __ldg(sl_row + k); n = i + 1; }
        else           { idxs[i] = 0; }
    }
    #pragma unroll
    for (int i = 0; i < MAX_ITERS; i++)
        bvs[i] = __ldg(bias + idxs[i]);        // idx 0 for inactive slots: valid addr

    // Lane-invariant embed slice in registers
    const float4 e0 = s_embed[lane +  0];
    const float4 e1 = s_embed[lane + 32];
    const float4 e2 = s_embed[lane + 64];
    const float4 e3 = s_embed[lane + 96];

    // ---- Prologue: fill up to STAGES rows into the per-warp smem ring.
    // Empty commit groups keep the group count aligned for inactive slots.
    #pragma unroll
    for (int s = 0; s < STAGES; s++) {
        if (s < n) {
            const float4* wrow =
                reinterpret_cast<const float4*>(weight + (size_t)idxs[s] * D_DIM);
            const uint32_t sb =
                (uint32_t)__cvta_generic_to_shared(&s_rows[warp][s][0]);
            cp_async16(sb + (uint32_t)(lane +  0) * 16, wrow + lane +  0);
            cp_async16(sb + (uint32_t)(lane + 32) * 16, wrow + lane + 32);
            cp_async16(sb + (uint32_t)(lane + 64) * 16, wrow + lane + 64);
            cp_async16(sb + (uint32_t)(lane + 96) * 16, wrow + lane + 96);
        }
        cp_commit();
    }

    // ---- Main loop: consume row i, refill stage with row i+STAGES.
    #pragma unroll
    for (int i = 0; i < MAX_ITERS; i++) {
        if (i >= n) break;

        cp_wait<STAGES - 1>();                 // row i's group has landed
        const int st = i & (STAGES - 1);

        // Each lane reads exactly the slots it cp.async'd (no cross-lane dep).
        const float4 w0 = s_rows[warp][st][lane +  0];
        const float4 w1 = s_rows[warp][st][lane + 32];
        const float4 w2 = s_rows[warp][st][lane + 64];
        const float4 w3 = s_rows[warp][st][lane + 96];

        float sum = w0.x * e0.x + w0.y * e0.y + w0.z * e0.z + w0.w * e0.w;
        sum      += w1.x * e1.x + w1.y * e1.y + w1.z * e1.z + w1.w * e1.w;
        sum      += w2.x * e2.x + w2.y * e2.y + w2.z * e2.z + w2.w * e2.w;
        sum      += w3.x * e3.x + w3.y * e3.y + w3.z * e3.z + w3.w * e3.w;

        // Refill this stage with row i+STAGES (issued before the serial
        // shfl reduction so the loads overlap it). The FMAs above already
        // forced the LDS reads to complete, so overwriting is safe.
        const int inext = i + STAGES;
        if (inext < n) {
            const float4* wrow =
                reinterpret_cast<const float4*>(weight + (size_t)idxs[inext] * D_DIM);
            const uint32_t sb =
                (uint32_t)__cvta_generic_to_shared(&s_rows[warp][st][0]);
            cp_async16(sb + (uint32_t)(lane +  0) * 16, wrow + lane +  0);
            cp_async16(sb + (uint32_t)(lane + 32) * 16, wrow + lane + 32);
            cp_async16(sb + (uint32_t)(lane + 64) * 16, wrow + lane + 64);
            cp_async16(sb + (uint32_t)(lane + 96) * 16, wrow + lane + 96);
        }
        cp_commit();

        // Warp butterfly reduction overlaps the in-flight cp.asyncs
        #pragma unroll
        for (int off = 16; off > 0; off >>= 1)
            sum += __shfl_xor_sync(0xFFFFFFFFu, sum, off);

        if (lane == 0)
            out[(size_t)b * K_DIM + k0 + i * WARPS] = sum + bvs[i];
    }
}

extern "C" void kernel_launch(void* const* d_in, const int* in_sizes, int n_in,
                              void* d_out, int out_size)
{
    const float* embed     = (const float*)d_in[0];  // [B, D] f32
    const int*   shortlist = (const int*)d_in[1];    // [B, K] i32
    const float* weight    = (const float*)d_in[2];  // [L, D] f32
    const float* bias      = (const float*)d_in[3];  // [L, 1] f32
    float*       out       = (float*)d_out;          // [B, K] f32

    dim3 grid(B_DIM, SPLITS);
    sparse_linear_kernel<<<grid, THREADS>>>(embed, shortlist, weight, bias, out);
}

// round 14
// speedup vs baseline: 1.0556x; 1.0062x over previous
#include <cuda_runtime.h>
#include <cstdint>

// SparseLinear: out[b,k] = dot(embed[b,:], weight[shortlist[b,k],:]) + bias[shortlist[b,k]]
// B=256, K=500, D=512, L=262144  (shortlist buffer is int32: JAX x64 disabled)
//
// R10 post-mortem: 43.5us, DRAM 67.7% — still latency-exposed; register
// double-buffer caps in-flight depth at 1 row/warp and costs occupancy.
// R12: cp.async.cg -> smem 4-deep per-warp ring. Depth now paid in smem, not
// registers: 24 warps/SM x 4 rows x 2KB ~ 192KB in flight per SM. Each lane
// copies and consumes ONLY its own 16B slots -> wait_group alone synchronizes,
// no cross-lane barriers in the loop.

#define B_DIM 256
#define K_DIM 500
#define D_DIM 512
#define SPLITS 16
#define K_PER_BLOCK ((K_DIM + SPLITS - 1) / SPLITS)   // 32
#define THREADS 128
#define WARPS (THREADS / 32)                          // 4
#define MAX_ITERS ((K_PER_BLOCK + WARPS - 1) / WARPS) // 8
#define STAGES 4
#define ROW_F4 (D_DIM / 4)                            // 128 float4 per row

__device__ __forceinline__ void cp_async16(uint32_t saddr, const void* gaddr) {
    asm volatile("cp.async.cg.shared.global [%0], [%1], 16;\n"
                 :: "r"(saddr), "l"(gaddr) : "memory");
}
__device__ __forceinline__ void cp_commit() {
    asm volatile("cp.async.commit_group;\n" ::: "memory");
}
template <int N>
__device__ __forceinline__ void cp_wait() {
    asm volatile("cp.async.wait_group %0;\n" :: "n"(N) : "memory");
}

__global__ __launch_bounds__(THREADS)
void sparse_linear_kernel(const float* __restrict__ embed,
                          const int* __restrict__ shortlist,
                          const float* __restrict__ weight,
                          const float* __restrict__ bias,
                          float* __restrict__ out)
{
    __shared__ float4 s_embed[ROW_F4];                    // 2 KB
    __shared__ float4 s_rows[WARPS][STAGES][ROW_F4];      // 32 KB

    const int b    = blockIdx.x;
    const int tid  = threadIdx.x;
    const int warp = tid >> 5;
    const int lane = tid & 31;

    // Cooperative load of embed[b] into smem (128 threads, one float4 each)
    const float4* embed_row = reinterpret_cast<const float4*>(embed + (size_t)b * D_DIM);
    s_embed[tid] = embed_row[tid];
    __syncthreads();

    const int k_begin = blockIdx.y * K_PER_BLOCK;
    int k_end = k_begin + K_PER_BLOCK;
    if (k_end > K_DIM) k_end = K_DIM;

    const int* sl_row = shortlist + (size_t)b * K_DIM;
    const int k0 = k_begin + warp;             // this warp's first k; stride = WARPS

    // ---- Prefetch all indices + biases for this warp (independent LDGs)
    int   idxs[MAX_ITERS];
    float bvs[MAX_ITERS];
    int   n = 0;
    #pragma unroll
    for (int i = 0; i < MAX_ITERS; i++) {
        const int k = k0 + i * WARPS;
        if (k < k_end) { idxs[i] = __ldg(sl_row + k); n = i + 1; }
        else           { idxs[i] = 0; }
    }
    #pragma unroll
    for (int i = 0; i < MAX_ITERS; i++)
        bvs[i] = __ldg(bias + idxs[i]);        // idx 0 for inactive slots: valid addr

    // Lane-invariant embed slice in registers
    const float4 e0 = s_embed[lane +  0];
    const float4 e1 = s_embed[lane + 32];
    const float4 e2 = s_embed[lane + 64];
    const float4 e3 = s_embed[lane + 96];

    // ---- Prologue: fill up to STAGES rows into the per-warp smem ring.
    // Empty commit groups keep the group count aligned for inactive slots.
    #pragma unroll
    for (int s = 0; s < STAGES; s++) {
        if (s < n) {
            const float4* wrow =
                reinterpret_cast<const float4*>(weight + (size_t)idxs[s] * D_DIM);
            const uint32_t sb =
                (uint32_t)__cvta_generic_to_shared(&s_rows[warp][s][0]);
            cp_async16(sb + (uint32_t)(lane +  0) * 16, wrow + lane +  0);
            cp_async16(sb + (uint32_t)(lane + 32) * 16, wrow + lane + 32);
            cp_async16(sb + (uint32_t)(lane + 64) * 16, wrow + lane + 64);
            cp_async16(sb + (uint32_t)(lane + 96) * 16, wrow + lane + 96);
        }
        cp_commit();
    }

    // ---- Main loop: consume row i, refill stage with row i+STAGES.
    #pragma unroll
    for (int i = 0; i < MAX_ITERS; i++) {
        if (i >= n) break;

        cp_wait<STAGES - 1>();                 // row i's group has landed
        const int st = i & (STAGES - 1);

        // Each lane reads exactly the slots it cp.async'd (no cross-lane dep).
        const float4 w0 = s_rows[warp][st][lane +  0];
        const float4 w1 = s_rows[warp][st][lane + 32];
        const float4 w2 = s_rows[warp][st][lane + 64];
        const float4 w3 = s_rows[warp][st][lane + 96];

        float sum = w0.x * e0.x + w0.y * e0.y + w0.z * e0.z + w0.w * e0.w;
        sum      += w1.x * e1.x + w1.y * e1.y + w1.z * e1.z + w1.w * e1.w;
        sum      += w2.x * e2.x + w2.y * e2.y + w2.z * e2.z + w2.w * e2.w;
        sum      += w3.x * e3.x + w3.y * e3.y + w3.z * e3.z + w3.w * e3.w;

        // Refill this stage with row i+STAGES (issued before the serial
        // shfl reduction so the loads overlap it). The FMAs above already
        // forced the LDS reads to complete, so overwriting is safe.
        const int inext = i + STAGES;
        if (inext < n) {
            const float4* wrow =
                reinterpret_cast<const float4*>(weight + (size_t)idxs[inext] * D_DIM);
            const uint32_t sb =
                (uint32_t)__cvta_generic_to_shared(&s_rows[warp][st][0]);
            cp_async16(sb + (uint32_t)(lane +  0) * 16, wrow + lane +  0);
            cp_async16(sb + (uint32_t)(lane + 32) * 16, wrow + lane + 32);
            cp_async16(sb + (uint32_t)(lane + 64) * 16, wrow + lane + 64);
            cp_async16(sb + (uint32_t)(lane + 96) * 16, wrow + lane + 96);
        }
        cp_commit();

        // Warp butterfly reduction overlaps the in-flight cp.asyncs
        #pragma unroll
        for (int off = 16; off > 0; off >>= 1)
            sum += __shfl_xor_sync(0xFFFFFFFFu, sum, off);

        if (lane == 0)
            out[(size_t)b * K_DIM + k0 + i * WARPS] = sum + bvs[i];
    }
}

extern "C" void kernel_launch(void* const* d_in, const int* in_sizes, int n_in,
                              void* d_out, int out_size)
{
    const float* embed     = (const float*)d_in[0];  // [B, D] f32
    const int*   shortlist = (const int*)d_in[1];    // [B, K] i32
    const float* weight    = (const float*)d_in[2];  // [L, D] f32
    const float* bias      = (const float*)d_in[3];  // [L, 1] f32
    float*       out       = (float*)d_out;          // [B, K] f32

    dim3 grid(B_DIM, SPLITS);
    sparse_linear_kernel<<<grid, THREADS>>>(embed, shortlist, weight, bias, out);
}